// round 8
// baseline (speedup 1.0000x reference)
#include <cuda_runtime.h>
#include <cstdint>

// FreezedScaledFakeQuantize: out = (clip(round(x/s + zp), qmin, qmax) - zp) * s
// X: [8192, 8192] fp32; scale/zp: [8192, 64] fp32 (group size 128); qmin/qmax: int32 scalars.
//
// R7 baseline: VPT=2 -> 75.3us kernel, DRAM 81.3%, issue 49%, occ 84%.
// Diagnosis: latency-exposed, not bandwidth- or issue-bound. This round:
// VECS_PER_THREAD 2 -> 4, all four 128-bit loads FRONT-BATCHED (per-warp MLP x2;
// net in-flight loads/SM ~107 -> ~160 despite occupancy dropping to ~60%).
//   - block owns 1024 contiguous vecs; thread t -> vecs t, t+256, t+512, t+768
//     (coalesced; each warp-access spans exactly one 128-elem group -> uniform s/zp)
//   - streaming hints: __ldcs on X, __stcs on out; scales via __ldg (L2-resident)
//   - EXACT __fdiv_rn + rintf: matches reference well under rel-err budget
//     (measured 1.8e-5) and divide is free at these pipe utilizations.

static constexpr int ROWS = 8192;
static constexpr int COLS = 8192;
static constexpr int GROUP_SIZE = 128;
static constexpr int N_GROUPS = COLS / GROUP_SIZE;         // 64
static constexpr int VECS_PER_ROW = COLS / 4;              // 2048
static constexpr unsigned TOTAL_VECS = (unsigned)ROWS * VECS_PER_ROW;  // 2^24

static constexpr int THREADS = 256;
static constexpr int VECS_PER_THREAD = 4;
static constexpr int VECS_PER_BLOCK = THREADS * VECS_PER_THREAD;  // 1024

__device__ __forceinline__ float4 fq4_exact(float4 x, float s, float zp,
                                            float qmin, float qmax)
{
    float q0 = rintf(__fdiv_rn(x.x, s) + zp);
    float q1 = rintf(__fdiv_rn(x.y, s) + zp);
    float q2 = rintf(__fdiv_rn(x.z, s) + zp);
    float q3 = rintf(__fdiv_rn(x.w, s) + zp);
    q0 = fminf(fmaxf(q0, qmin), qmax);
    q1 = fminf(fmaxf(q1, qmin), qmax);
    q2 = fminf(fmaxf(q2, qmin), qmax);
    q3 = fminf(fmaxf(q3, qmin), qmax);
    float4 r;
    r.x = (q0 - zp) * s;
    r.y = (q1 - zp) * s;
    r.z = (q2 - zp) * s;
    r.w = (q3 - zp) * s;
    return r;
}

__global__ __launch_bounds__(THREADS)
void fake_quantize_kernel(const float* __restrict__ X,
                          const float* __restrict__ scale,
                          const float* __restrict__ zero_point,
                          const int* __restrict__ qmin_p,
                          const int* __restrict__ qmax_p,
                          float* __restrict__ out)
{
    const unsigned base = blockIdx.x * VECS_PER_BLOCK + threadIdx.x;
    const unsigned vid0 = base;
    const unsigned vid1 = base + THREADS;
    const unsigned vid2 = base + 2 * THREADS;
    const unsigned vid3 = base + 3 * THREADS;

    // Front-batched independent 128-bit streaming loads -> MLP=4 per thread
    const float4 x0 = __ldcs(((const float4*)X) + vid0);
    const float4 x1 = __ldcs(((const float4*)X) + vid1);
    const float4 x2 = __ldcs(((const float4*)X) + vid2);
    const float4 x3 = __ldcs(((const float4*)X) + vid3);

    const float qmin = (float)__ldg(qmin_p);
    const float qmax = (float)__ldg(qmax_p);

    // Power-of-2 index math -> shifts/masks; warp-uniform per access
    const unsigned row0 = vid0 >> 11, grp0 = (vid0 & (VECS_PER_ROW - 1)) >> 5;
    const unsigned row1 = vid1 >> 11, grp1 = (vid1 & (VECS_PER_ROW - 1)) >> 5;
    const unsigned row2 = vid2 >> 11, grp2 = (vid2 & (VECS_PER_ROW - 1)) >> 5;
    const unsigned row3 = vid3 >> 11, grp3 = (vid3 & (VECS_PER_ROW - 1)) >> 5;

    const float s0  = __ldg(&scale[row0 * N_GROUPS + grp0]);
    const float zp0 = __ldg(&zero_point[row0 * N_GROUPS + grp0]);
    const float s1  = __ldg(&scale[row1 * N_GROUPS + grp1]);
    const float zp1 = __ldg(&zero_point[row1 * N_GROUPS + grp1]);
    const float s2  = __ldg(&scale[row2 * N_GROUPS + grp2]);
    const float zp2 = __ldg(&zero_point[row2 * N_GROUPS + grp2]);
    const float s3  = __ldg(&scale[row3 * N_GROUPS + grp3]);
    const float zp3 = __ldg(&zero_point[row3 * N_GROUPS + grp3]);

    const float4 r0 = fq4_exact(x0, s0, zp0, qmin, qmax);
    const float4 r1 = fq4_exact(x1, s1, zp1, qmin, qmax);
    const float4 r2 = fq4_exact(x2, s2, zp2, qmin, qmax);
    const float4 r3 = fq4_exact(x3, s3, zp3, qmin, qmax);

    __stcs(((float4*)out) + vid0, r0);
    __stcs(((float4*)out) + vid1, r1);
    __stcs(((float4*)out) + vid2, r2);
    __stcs(((float4*)out) + vid3, r3);
}

extern "C" void kernel_launch(void* const* d_in, const int* in_sizes, int n_in,
                              void* d_out, int out_size)
{
    const float* X          = (const float*)d_in[0];
    const float* scale      = (const float*)d_in[1];
    const float* zero_point = (const float*)d_in[2];
    const int*   qmin       = (const int*)d_in[3];
    const int*   qmax       = (const int*)d_in[4];
    float*       out        = (float*)d_out;

    const unsigned blocks = TOTAL_VECS / VECS_PER_BLOCK;  // 16384, exact division
    fake_quantize_kernel<<<blocks, THREADS>>>(X, scale, zero_point, qmin, qmax, out);
}

// round 16
// speedup vs baseline: 1.0012x; 1.0012x over previous
#include <cuda_runtime.h>
#include <cstdint>

// FreezedScaledFakeQuantize: out = (clip(round(x/s + zp), qmin, qmax) - zp) * s
// X: [8192, 8192] fp32; scale/zp: [8192, 64] fp32 (group size 128); qmin/qmax: int32 scalars.
//
// Measured so far (GB300):
//   R7: VPT=2, ldcs/stcs, occ 84%  -> kernel 75.33us, DRAM 81.3%, 6.44 TB/s
//   R8: VPT=4, ldcs/stcs, occ 64%  -> kernel 75.36us, DRAM 81.2%, 6.43 TB/s
// Occupancy x MLP had ZERO effect -> kernel is at the achieved-DRAM ceiling for a
// mixed read+write stream (~80% of spec). This round (7th retry after infra
// timeouts): same R7 shape, DEFAULT cache policy (no ldcs/stcs) -- the last
// untested axis. Expect ~no change; if so, declare roofline and freeze.
//
//   - 2x independent float4 loads per thread, front-batched (VPT=2, 32 regs)
//   - block owns 512 contiguous vecs; warp-access spans one 128-elem group
//     -> warp-uniform scale/zp via __ldg (2 MiB, L2-resident)
//   - EXACT __fdiv_rn + rintf (measured rel_err 1.8e-5, budget 1e-3)
//   - pure 32-bit index math

static constexpr int ROWS = 8192;
static constexpr int COLS = 8192;
static constexpr int GROUP_SIZE = 128;
static constexpr int N_GROUPS = COLS / GROUP_SIZE;         // 64
static constexpr int VECS_PER_ROW = COLS / 4;              // 2048
static constexpr unsigned TOTAL_VECS = (unsigned)ROWS * VECS_PER_ROW;  // 2^24

static constexpr int THREADS = 256;
static constexpr int VECS_PER_THREAD = 2;
static constexpr int VECS_PER_BLOCK = THREADS * VECS_PER_THREAD;  // 512

__device__ __forceinline__ float4 fq4_exact(float4 x, float s, float zp,
                                            float qmin, float qmax)
{
    float q0 = rintf(__fdiv_rn(x.x, s) + zp);
    float q1 = rintf(__fdiv_rn(x.y, s) + zp);
    float q2 = rintf(__fdiv_rn(x.z, s) + zp);
    float q3 = rintf(__fdiv_rn(x.w, s) + zp);
    q0 = fminf(fmaxf(q0, qmin), qmax);
    q1 = fminf(fmaxf(q1, qmin), qmax);
    q2 = fminf(fmaxf(q2, qmin), qmax);
    q3 = fminf(fmaxf(q3, qmin), qmax);
    float4 r;
    r.x = (q0 - zp) * s;
    r.y = (q1 - zp) * s;
    r.z = (q2 - zp) * s;
    r.w = (q3 - zp) * s;
    return r;
}

__global__ __launch_bounds__(THREADS)
void fake_quantize_kernel(const float* __restrict__ X,
                          const float* __restrict__ scale,
                          const float* __restrict__ zero_point,
                          const int* __restrict__ qmin_p,
                          const int* __restrict__ qmax_p,
                          float* __restrict__ out)
{
    const unsigned vid0 = blockIdx.x * VECS_PER_BLOCK + threadIdx.x;
    const unsigned vid1 = vid0 + THREADS;

    // Front-batched independent 128-bit loads (default cache policy this round)
    const float4 x0 = ((const float4*)X)[vid0];
    const float4 x1 = ((const float4*)X)[vid1];

    const float qmin = (float)__ldg(qmin_p);
    const float qmax = (float)__ldg(qmax_p);

    const unsigned row0 = vid0 >> 11, grp0 = (vid0 & (VECS_PER_ROW - 1)) >> 5;
    const unsigned row1 = vid1 >> 11, grp1 = (vid1 & (VECS_PER_ROW - 1)) >> 5;

    const float s0  = __ldg(&scale[row0 * N_GROUPS + grp0]);
    const float zp0 = __ldg(&zero_point[row0 * N_GROUPS + grp0]);
    const float s1  = __ldg(&scale[row1 * N_GROUPS + grp1]);
    const float zp1 = __ldg(&zero_point[row1 * N_GROUPS + grp1]);

    const float4 r0 = fq4_exact(x0, s0, zp0, qmin, qmax);
    const float4 r1 = fq4_exact(x1, s1, zp1, qmin, qmax);

    ((float4*)out)[vid0] = r0;
    ((float4*)out)[vid1] = r1;
}

extern "C" void kernel_launch(void* const* d_in, const int* in_sizes, int n_in,
                              void* d_out, int out_size)
{
    const float* X          = (const float*)d_in[0];
    const float* scale      = (const float*)d_in[1];
    const float* zero_point = (const float*)d_in[2];
    const int*   qmin       = (const int*)d_in[3];
    const int*   qmax       = (const int*)d_in[4];
    float*       out        = (float*)d_out;

    const unsigned blocks = TOTAL_VECS / VECS_PER_BLOCK;  // 32768
    fake_quantize_kernel<<<blocks, THREADS>>>(X, scale, zero_point, qmin, qmax, out);
}